// round 4
// baseline (speedup 1.0000x reference)
#include <cuda_runtime.h>
#include <math_constants.h>

#define NB        16
#define NPTS      4096
#define SPLITS    8
#define REFS_PB   (NPTS / SPLITS)     // 512 refs per block
#define RPAIRS_PB (REFS_PB / 2)       // 256 packed ref pairs per block
#define THREADS   64
#define QPT       8
#define QPB       (THREADS * QPT)     // 512 queries per block
#define QBLKS     (NPTS / QPB)        // 8
#define TQ        (2 * NB * NPTS)     // 131072 queries total (both dirs)
#define CBLOCKS   256

typedef unsigned long long u64;

__device__ __forceinline__ u64 fma2(u64 a, u64 b, u64 c) {
    u64 d;
    asm("fma.rn.f32x2 %0, %1, %2, %3;" : "=l"(d) : "l"(a), "l"(b), "l"(c));
    return d;
}
union f2u { float2 f; u64 u; };
__device__ __forceinline__ u64 splat2(float v) { f2u t; t.f = make_float2(v, v); return t.u; }

// Scratch (no cudaMalloc allowed). Planar: g_minpart[split * TQ + globalQuery]
__device__ float g_minpart[SPLITS * TQ];   // 4 MB
__device__ float g_partials[CBLOCKS];
__device__ int   g_count = 0;

// grid = (QBLKS*SPLITS, NB, 2). 512 queries x 512 refs per block, one 8KB tile.
// Tile filled straight from raw input (||r||^2 computed inline). Writes
// per-query partial mins (excluding ||q||^2) to planar g_minpart.
__global__ void __launch_bounds__(THREADS)
chamfer_kernel(const float* __restrict__ p1, const float* __restrict__ p2) {
    __shared__ float4 tile[2 * RPAIRS_PB];   // pair p: [2p]={x0,x1,y0,y1} [2p+1]={z0,z1,w0,w1}

    const int dir   = blockIdx.z;
    const int b     = blockIdx.y;
    const int qblk  = blockIdx.x / SPLITS;
    const int split = blockIdx.x % SPLITS;

    const float* __restrict__ qsrc = dir ? p2 : p1;   // queries come from own cloud
    const float* __restrict__ rsrc = dir ? p1 : p2;   // refs from the other cloud

    // Fill tile from raw floats: 3 float2 loads per pair, compute norms inline.
    const float2* __restrict__ r2 =
        (const float2*)(rsrc + (size_t)(b * NPTS + split * REFS_PB) * 3);
    #pragma unroll
    for (int jp = threadIdx.x; jp < RPAIRS_PB; jp += THREADS) {
        float2 f0 = r2[3 * jp], f1 = r2[3 * jp + 1], fz = r2[3 * jp + 2];
        float x0 = f0.x, y0 = f0.y, z0 = f1.x;
        float x1 = f1.y, y1 = fz.x, z1 = fz.y;
        tile[2 * jp + 0] = make_float4(x0, x1, y0, y1);
        tile[2 * jp + 1] = make_float4(z0, z1,
                                       fmaf(x0, x0, fmaf(y0, y0, z0 * z0)),
                                       fmaf(x1, x1, fmaf(y1, y1, z1 * z1)));
    }

    // Load 8 queries, splat -2*q components (while the fill lands).
    const int qi0 = qblk * QPB + threadIdx.x;   // query index within batch
    const float* __restrict__ qb = qsrc + (size_t)(b * NPTS + qi0) * 3;
    u64 sX[QPT], sY[QPT], sZ[QPT];
    #pragma unroll
    for (int k = 0; k < QPT; k++) {
        const float* qp = qb + k * THREADS * 3;
        sX[k] = splat2(-2.0f * qp[0]);
        sY[k] = splat2(-2.0f * qp[1]);
        sZ[k] = splat2(-2.0f * qp[2]);
    }
    float2 acc[QPT];
    #pragma unroll
    for (int k = 0; k < QPT; k++) acc[k] = make_float2(CUDART_INF_F, CUDART_INF_F);

    __syncthreads();

    // Hot loop: per ref-pair = 2 broadcast LDS.128 + 24 FFMA2 + 16 FMNMX
    // for 16 pair-distances. FFMA2 (fma pipe, rt=2) is the binding resource.
    const ulonglong2* __restrict__ tp = (const ulonglong2*)tile;
    #pragma unroll 2
    for (int j = 0; j < RPAIRS_PB; j++) {
        ulonglong2 xy = tp[2 * j];       // {x0,x1},{y0,y1}
        ulonglong2 zw = tp[2 * j + 1];   // {z0,z1},{w0,w1}
        #pragma unroll
        for (int k = 0; k < QPT; k++) {
            f2u d;
            d.u = fma2(sX[k], xy.x, fma2(sY[k], xy.y, fma2(sZ[k], zw.x, zw.y)));
            acc[k].x = fminf(acc[k].x, d.f.x);
            acc[k].y = fminf(acc[k].y, d.f.y);
        }
    }

    // Coalesced planar writes.
    const int gq = (dir * NB + b) * NPTS + qi0;
    float* __restrict__ mp = g_minpart + (size_t)split * TQ + gq;
    #pragma unroll
    for (int k = 0; k < QPT; k++)
        mp[k * THREADS] = fminf(acc[k].x, acc[k].y);
}

// Fused combine + final reduce. Each block: 512 queries -> partial sum.
// Last block (threadfence+counter) sums the 256 partials deterministically.
__global__ void __launch_bounds__(256)
combine_reduce_kernel(const float* __restrict__ p1, const float* __restrict__ p2,
                      float* __restrict__ out) {
    __shared__ float ssum[8];
    __shared__ int   s_last;

    float v = 0.0f;
    #pragma unroll
    for (int r = 0; r < 2; r++) {
        int g = blockIdx.x * 512 + r * 256 + threadIdx.x;   // global query id
        float mn = CUDART_INF_F;
        #pragma unroll
        for (int s = 0; s < SPLITS; s++)
            mn = fminf(mn, g_minpart[(size_t)s * TQ + g]);
        int side = g >> 16;                 // NB*NPTS = 65536
        int li   = g & 65535;
        const float* P = side ? p2 : p1;
        float x = P[3 * li], y = P[3 * li + 1], z = P[3 * li + 2];
        v += mn + fmaf(x, x, fmaf(y, y, z * z));
    }
    #pragma unroll
    for (int o = 16; o > 0; o >>= 1)
        v += __shfl_down_sync(0xFFFFFFFFu, v, o);
    if ((threadIdx.x & 31) == 0) ssum[threadIdx.x >> 5] = v;
    __syncthreads();

    if (threadIdx.x == 0) {
        float s = 0.0f;
        #pragma unroll
        for (int w = 0; w < 8; w++) s += ssum[w];
        g_partials[blockIdx.x] = s;
        __threadfence();
        int rank = atomicAdd(&g_count, 1);
        s_last = (rank == CBLOCKS - 1);
    }
    __syncthreads();

    if (s_last) {
        float t = g_partials[threadIdx.x];   // CBLOCKS == blockDim.x == 256
        #pragma unroll
        for (int o = 16; o > 0; o >>= 1)
            t += __shfl_down_sync(0xFFFFFFFFu, t, o);
        if ((threadIdx.x & 31) == 0) ssum[threadIdx.x >> 5] = t;
        __syncthreads();
        if (threadIdx.x == 0) {
            float s = 0.0f;
            #pragma unroll
            for (int w = 0; w < 8; w++) s += ssum[w];
            out[0] = s * (1.0f / (float)NB);
            g_count = 0;                     // reset for next graph replay
        }
    }
}

extern "C" void kernel_launch(void* const* d_in, const int* in_sizes, int n_in,
                              void* d_out, int out_size) {
    const float* p1 = (const float*)d_in[0];
    const float* p2 = (const float*)d_in[1];
    float* out = (float*)d_out;

    dim3 grid(QBLKS * SPLITS, NB, 2);   // 64 x 16 x 2 = 2048 blocks
    chamfer_kernel<<<grid, THREADS>>>(p1, p2);

    combine_reduce_kernel<<<CBLOCKS, 256>>>(p1, p2, out);
}

// round 5
// speedup vs baseline: 1.0022x; 1.0022x over previous
#include <cuda_runtime.h>
#include <math_constants.h>

#define NB        16
#define NPTS      4096
#define SPLITS    4
#define REFS_PB   (NPTS / SPLITS)     // 1024 refs per block
#define RPAIRS_PB (REFS_PB / 2)       // 512 packed ref pairs = 16KB tile
#define THREADS   128
#define QPT       4
#define QPB       (THREADS * QPT)     // 512 queries per block
#define QBLKS     (NPTS / QPB)        // 8
#define TQ        (2 * NB * NPTS)     // 131072 queries total (both dirs)
#define CBLOCKS   512

typedef unsigned long long u64;

__device__ __forceinline__ u64 fma2(u64 a, u64 b, u64 c) {
    u64 d;
    asm("fma.rn.f32x2 %0, %1, %2, %3;" : "=l"(d) : "l"(a), "l"(b), "l"(c));
    return d;
}
union f2u { float2 f; u64 u; };
__device__ __forceinline__ u64 splat2(float v) { f2u t; t.f = make_float2(v, v); return t.u; }

// Scratch (no cudaMalloc). Planar: g_minpart[split * TQ + globalQuery]
__device__ float g_minpart[SPLITS * TQ];   // 2 MB
__device__ float g_partials[CBLOCKS];
__device__ int   g_count = 0;

// grid = (QBLKS*SPLITS, NB, 2). 512 queries x 1024 refs per block.
// Per-iteration per-warp: 2 broadcast LDS.128 + 12 FFMA2 (rt=3, binding)
// + 8 FMNMX (alu). Writes per-query partial mins (excl ||q||^2).
__global__ void __launch_bounds__(THREADS)
chamfer_kernel(const float* __restrict__ p1, const float* __restrict__ p2) {
    __shared__ float4 tile[2 * RPAIRS_PB];   // pair p: [2p]={x0,x1,y0,y1} [2p+1]={z0,z1,w0,w1}

    const int dir   = blockIdx.z;
    const int b     = blockIdx.y;
    const int qblk  = blockIdx.x / SPLITS;
    const int split = blockIdx.x % SPLITS;

    const float* __restrict__ qsrc = dir ? p2 : p1;
    const float* __restrict__ rsrc = dir ? p1 : p2;

    // Fill tile from raw input: 3 float2 loads per pair, norms inline.
    const float2* __restrict__ r2 =
        (const float2*)(rsrc + (size_t)(b * NPTS + split * REFS_PB) * 3);
    #pragma unroll
    for (int jp = threadIdx.x; jp < RPAIRS_PB; jp += THREADS) {
        float2 f0 = r2[3 * jp], f1 = r2[3 * jp + 1], fz = r2[3 * jp + 2];
        float x0 = f0.x, y0 = f0.y, z0 = f1.x;
        float x1 = f1.y, y1 = fz.x, z1 = fz.y;
        tile[2 * jp + 0] = make_float4(x0, x1, y0, y1);
        tile[2 * jp + 1] = make_float4(z0, z1,
                                       fmaf(x0, x0, fmaf(y0, y0, z0 * z0)),
                                       fmaf(x1, x1, fmaf(y1, y1, z1 * z1)));
    }

    // Load 4 queries, splat -2*q components (overlaps the fill).
    const int qi0 = qblk * QPB + threadIdx.x;
    const float* __restrict__ qb = qsrc + (size_t)(b * NPTS + qi0) * 3;
    u64 sX[QPT], sY[QPT], sZ[QPT];
    #pragma unroll
    for (int k = 0; k < QPT; k++) {
        const float* qp = qb + k * THREADS * 3;
        sX[k] = splat2(-2.0f * qp[0]);
        sY[k] = splat2(-2.0f * qp[1]);
        sZ[k] = splat2(-2.0f * qp[2]);
    }
    float2 acc[QPT];
    #pragma unroll
    for (int k = 0; k < QPT; k++) acc[k] = make_float2(CUDART_INF_F, CUDART_INF_F);

    __syncthreads();

    const ulonglong2* __restrict__ tp = (const ulonglong2*)tile;
    #pragma unroll 4
    for (int j = 0; j < RPAIRS_PB; j++) {
        ulonglong2 xy = tp[2 * j];       // {x0,x1},{y0,y1}
        ulonglong2 zw = tp[2 * j + 1];   // {z0,z1},{w0,w1}
        #pragma unroll
        for (int k = 0; k < QPT; k++) {
            f2u d;
            d.u = fma2(sX[k], xy.x, fma2(sY[k], xy.y, fma2(sZ[k], zw.x, zw.y)));
            acc[k].x = fminf(acc[k].x, d.f.x);
            acc[k].y = fminf(acc[k].y, d.f.y);
        }
    }

    // Coalesced planar writes.
    const int gq = (dir * NB + b) * NPTS + qi0;
    float* __restrict__ mp = g_minpart + (size_t)split * TQ + gq;
    #pragma unroll
    for (int k = 0; k < QPT; k++)
        mp[k * THREADS] = fminf(acc[k].x, acc[k].y);
}

// Combine splits -> per-query min, add ||q||^2, block-sum; last block
// (threadfence + counter) makes the final deterministic sum.
__global__ void __launch_bounds__(256)
combine_reduce_kernel(const float* __restrict__ p1, const float* __restrict__ p2,
                      float* __restrict__ out) {
    __shared__ float ssum[8];
    __shared__ int   s_last;

    const int g = blockIdx.x * 256 + threadIdx.x;   // global query id
    float mn = g_minpart[g];
    #pragma unroll
    for (int s = 1; s < SPLITS; s++)
        mn = fminf(mn, g_minpart[(size_t)s * TQ + g]);
    const int side = g >> 16;                 // NB*NPTS = 65536
    const int li   = g & 65535;
    const float* P = side ? p2 : p1;
    float x = P[3 * li], y = P[3 * li + 1], z = P[3 * li + 2];
    float v = mn + fmaf(x, x, fmaf(y, y, z * z));

    #pragma unroll
    for (int o = 16; o > 0; o >>= 1)
        v += __shfl_down_sync(0xFFFFFFFFu, v, o);
    if ((threadIdx.x & 31) == 0) ssum[threadIdx.x >> 5] = v;
    __syncthreads();

    if (threadIdx.x == 0) {
        float s = 0.0f;
        #pragma unroll
        for (int w = 0; w < 8; w++) s += ssum[w];
        g_partials[blockIdx.x] = s;
        __threadfence();
        int rank = atomicAdd(&g_count, 1);
        s_last = (rank == CBLOCKS - 1);
    }
    __syncthreads();

    if (s_last) {
        float t = g_partials[threadIdx.x] + g_partials[threadIdx.x + 256];
        #pragma unroll
        for (int o = 16; o > 0; o >>= 1)
            t += __shfl_down_sync(0xFFFFFFFFu, t, o);
        if ((threadIdx.x & 31) == 0) ssum[threadIdx.x >> 5] = t;
        __syncthreads();
        if (threadIdx.x == 0) {
            float s = 0.0f;
            #pragma unroll
            for (int w = 0; w < 8; w++) s += ssum[w];
            out[0] = s * (1.0f / (float)NB);
            g_count = 0;                     // reset for next graph replay
        }
    }
}

extern "C" void kernel_launch(void* const* d_in, const int* in_sizes, int n_in,
                              void* d_out, int out_size) {
    const float* p1 = (const float*)d_in[0];
    const float* p2 = (const float*)d_in[1];
    float* out = (float*)d_out;

    dim3 grid(QBLKS * SPLITS, NB, 2);   // 32 x 16 x 2 = 1024 blocks
    chamfer_kernel<<<grid, THREADS>>>(p1, p2);

    combine_reduce_kernel<<<CBLOCKS, 256>>>(p1, p2, out);
}

// round 6
// speedup vs baseline: 1.2639x; 1.2611x over previous
#include <cuda_runtime.h>
#include <math_constants.h>

#define NB       16
#define NPTS     4096
#define K        8                     // refs per lane (register-resident)
#define WARPS    4
#define THREADS  (WARPS * 32)          // 128
#define REFS_PW  (32 * K)              // 256 refs per warp
#define REFS_PB  (WARPS * REFS_PW)     // 1024 refs per block
#define RCHUNKS  (NPTS / REFS_PB)      // 4
#define QC       256                   // queries per block
#define QPAIRS   (QC / 2)              // 128
#define QCHUNKS  (NPTS / QC)           // 16
#define NQ       (NB * NPTS)           // 65536 points per cloud
#define CBLOCKS  512

typedef unsigned long long u64;

__device__ __forceinline__ u64 fma2(u64 a, u64 b, u64 c) {
    u64 d;
    asm("fma.rn.f32x2 %0, %1, %2, %3;" : "=l"(d) : "l"(a), "l"(b), "l"(c));
    return d;
}
__device__ __forceinline__ u64 add2(u64 a, u64 b) {
    u64 d;
    asm("add.rn.f32x2 %0, %1, %2;" : "=l"(d) : "l"(a), "l"(b));
    return d;
}
union f2u { float2 f; u64 u; };
__device__ __forceinline__ u64 splat2(float v) { f2u t; t.f = make_float2(v, v); return t.u; }

// Scratch (no cudaMalloc). Each full distance d(q,r) is computed ONCE and
// feeds both directions' mins.
__device__ float g_rowpart[RCHUNKS][NQ];   // p1-side partial mins (1 MB)
__device__ float g_colpart[QCHUNKS][NQ];   // p2-side partial mins (4 MB)
__device__ float g_partials[CBLOCKS];
__device__ int   g_count = 0;

// grid = (RCHUNKS*QCHUNKS, NB) = (64, 16) = 1024 blocks.
// Block: 1024 p2 refs in registers (K=8 per lane, 4 warps) x 256 p1 queries
// streamed from smem as pairs. Per ref per query-pair:
//   3 FFMA2 (+wr splat innermost) + 1 FADD2 (+wq pair) -> full dist pair
//   2 FMNMX -> colmin (lane-resident), 2 FMNMX -> rowmin (packed accums)
// Butterfly per query-pair gives warp rowmin; warps combined via smem.
__global__ void __launch_bounds__(THREADS)
chamfer_kernel(const float* __restrict__ p1, const float* __restrict__ p2) {
    __shared__ float4 qt[2 * QPAIRS];            // 4 KB query tile (pairs)
    __shared__ float2 stage[WARPS][QPAIRS];      // 4 KB warp rowmin staging

    const int rc   = blockIdx.x & (RCHUNKS - 1);
    const int qc   = blockIdx.x >> 2;
    const int b    = blockIdx.y;
    const int lane = threadIdx.x & 31;
    const int wid  = threadIdx.x >> 5;

    // ---- Load this lane's K refs from p2, build splat registers ----
    u64 mrx[K], mry[K], mrz[K], rw[K];
    const int rbase = b * NPTS + rc * REFS_PB + wid * REFS_PW + lane;
    #pragma unroll
    for (int k = 0; k < K; k++) {
        const float* r = p2 + (size_t)(rbase + k * 32) * 3;
        float x = r[0], y = r[1], z = r[2];
        mrx[k] = splat2(-2.0f * x);
        mry[k] = splat2(-2.0f * y);
        mrz[k] = splat2(-2.0f * z);
        rw[k]  = splat2(fmaf(x, x, fmaf(y, y, z * z)));
    }

    // ---- Build query tile: pair p = queries (2p, 2p+1) from p1 ----
    {
        int p = threadIdx.x;                      // THREADS == QPAIRS
        const float* q = p1 + (size_t)(b * NPTS + qc * QC + 2 * p) * 3;
        float2 f0 = ((const float2*)q)[0];
        float2 f1 = ((const float2*)q)[1];
        float2 f2 = ((const float2*)q)[2];
        float xA = f0.x, yA = f0.y, zA = f1.x;
        float xB = f1.y, yB = f2.x, zB = f2.y;
        qt[2 * p + 0] = make_float4(xA, xB, yA, yB);
        qt[2 * p + 1] = make_float4(zA, zB,
                                    fmaf(xA, xA, fmaf(yA, yA, zA * zA)),
                                    fmaf(xB, xB, fmaf(yB, yB, zB * zB)));
    }

    float colmin[K];
    #pragma unroll
    for (int k = 0; k < K; k++) colmin[k] = CUDART_INF_F;

    __syncthreads();

    const ulonglong2* __restrict__ qp = (const ulonglong2*)qt;
    for (int p = 0; p < QPAIRS; p++) {
        ulonglong2 A = qp[2 * p];       // A.x={xA,xB}  A.y={yA,yB}
        ulonglong2 B = qp[2 * p + 1];   // B.x={zA,zB}  B.y={wqA,wqB}
        float rA = CUDART_INF_F, rB = CUDART_INF_F;
        #pragma unroll
        for (int k = 0; k < K; k++) {
            f2u d;
            d.u = add2(fma2(mrx[k], A.x,
                       fma2(mry[k], A.y,
                       fma2(mrz[k], B.x, rw[k]))), B.y);   // full d pair
            colmin[k] = fminf(colmin[k], fminf(d.f.x, d.f.y));
            rA = fminf(rA, d.f.x);
            rB = fminf(rB, d.f.y);
        }
        // Warp rowmin over this warp's 256 refs.
        #pragma unroll
        for (int o = 16; o > 0; o >>= 1) {
            rA = fminf(rA, __shfl_xor_sync(0xFFFFFFFFu, rA, o));
            rB = fminf(rB, __shfl_xor_sync(0xFFFFFFFFu, rB, o));
        }
        if (lane == 0) stage[wid][p] = make_float2(rA, rB);
    }
    __syncthreads();

    // ---- Combine 4 warps' rowmins -> g_rowpart[rc] ----
    const float* st = (const float*)stage;
    for (int q = threadIdx.x; q < QC; q += THREADS) {
        float m = st[q];                                   // warp 0
        #pragma unroll
        for (int w = 1; w < WARPS; w++)
            m = fminf(m, st[w * QC + q]);
        g_rowpart[rc][b * NPTS + qc * QC + q] = m;
    }

    // ---- Col mins (complete over this query chunk) -> g_colpart[qc] ----
    #pragma unroll
    for (int k = 0; k < K; k++)
        g_colpart[qc][rbase + k * 32] = colmin[k];
}

// Combine partials -> per-point min, block-sum; last block does the final
// deterministic reduction (counter reset for graph replay).
__global__ void __launch_bounds__(256)
combine_reduce_kernel(float* __restrict__ out) {
    __shared__ float ssum[8];
    __shared__ int   s_last;

    const int g = blockIdx.x * 256 + threadIdx.x;   // [0, 2*NQ)
    float mn;
    if (g < NQ) {                                   // p1-side: 4 splits
        mn = g_rowpart[0][g];
        #pragma unroll
        for (int s = 1; s < RCHUNKS; s++) mn = fminf(mn, g_rowpart[s][g]);
    } else {                                        // p2-side: 16 splits
        int i = g - NQ;
        mn = g_colpart[0][i];
        #pragma unroll
        for (int s = 1; s < QCHUNKS; s++) mn = fminf(mn, g_colpart[s][i]);
    }
    float v = mn;

    #pragma unroll
    for (int o = 16; o > 0; o >>= 1)
        v += __shfl_down_sync(0xFFFFFFFFu, v, o);
    if ((threadIdx.x & 31) == 0) ssum[threadIdx.x >> 5] = v;
    __syncthreads();

    if (threadIdx.x == 0) {
        float s = 0.0f;
        #pragma unroll
        for (int w = 0; w < 8; w++) s += ssum[w];
        g_partials[blockIdx.x] = s;
        __threadfence();
        int rank = atomicAdd(&g_count, 1);
        s_last = (rank == CBLOCKS - 1);
    }
    __syncthreads();

    if (s_last) {
        float t = g_partials[threadIdx.x] + g_partials[threadIdx.x + 256];
        #pragma unroll
        for (int o = 16; o > 0; o >>= 1)
            t += __shfl_down_sync(0xFFFFFFFFu, t, o);
        if ((threadIdx.x & 31) == 0) ssum[threadIdx.x >> 5] = t;
        __syncthreads();
        if (threadIdx.x == 0) {
            float s = 0.0f;
            #pragma unroll
            for (int w = 0; w < 8; w++) s += ssum[w];
            out[0] = s * (1.0f / (float)NB);
            g_count = 0;
        }
    }
}

extern "C" void kernel_launch(void* const* d_in, const int* in_sizes, int n_in,
                              void* d_out, int out_size) {
    const float* p1 = (const float*)d_in[0];
    const float* p2 = (const float*)d_in[1];
    float* out = (float*)d_out;

    dim3 grid(RCHUNKS * QCHUNKS, NB);   // 64 x 16 = 1024 blocks
    chamfer_kernel<<<grid, THREADS>>>(p1, p2);

    combine_reduce_kernel<<<CBLOCKS, 256>>>(out);
}